// round 14
// baseline (speedup 1.0000x reference)
#include <cuda_runtime.h>
#include <math.h>

#define B 16
#define L 128
#define H 1024
#define V 50257
#define T (L-1)
#define BP (B/2)
#define NQ 12563             // quads per row; 4*NQ = 50252
#define NBLK 296             // exactly 2 CTAs/SM x 148 -> all co-resident
#define NCHUNK 1571          // ceil(V/32): k4 vocab chunks (8 warps x 4 rows)
#define NTASK ((NQ + 1) * B) // sum/store tasks

typedef unsigned long long u64;

// ---- scratch (no allocations allowed) ----
__device__ float g_x0[B * H];
__device__ float g_h0[B * H];
__device__ float g_gi[B * 3 * H];
__device__ float g_gh[B * 3 * H];
__device__ float g_h1[B * H];
__device__ float g_logits[(size_t)B * V];
__device__ float g_sum[B];

// grid barrier state (generation counter -> graph-replay safe)
__device__ volatile unsigned g_bar_gen;
__device__ unsigned g_bar_cnt;

__device__ __forceinline__ void grid_barrier() {
    __syncthreads();
    if (threadIdx.x == 0) {
        unsigned gen = g_bar_gen;
        __threadfence();
        if (atomicAdd(&g_bar_cnt, 1) == (unsigned)(NBLK - 1)) {
            g_bar_cnt = 0;
            __threadfence();
            g_bar_gen = gen + 1;
        } else {
            while (g_bar_gen == gen) { }
        }
    }
    __syncthreads();
}

// packed f32x2 FMA: d = a*b + d (2 MACs / SASS FFMA2)
__device__ __forceinline__ void ffma2(u64 &d, u64 a, u64 b) {
    asm("fma.rn.f32x2 %0, %1, %2, %0;" : "+l"(d) : "l"(a), "l"(b));
}
__device__ __forceinline__ u64 dup2(float f) {
    u64 r;
    asm("mov.b64 %0, {%1, %1};" : "=l"(r) : "f"(f));
    return r;
}
__device__ __forceinline__ float lo2(u64 a) { return __uint_as_float((unsigned)a); }
__device__ __forceinline__ float hi2(u64 a) { return __uint_as_float((unsigned)(a >> 32)); }

// XOR swizzle on u64 index: flips the 16B-granule bit on alternating 128B lines
__device__ __forceinline__ int swz(int i) { return i ^ (((i >> 4) & 1) << 1); }

// cp.async 16B, L2-only path (streaming)
__device__ __forceinline__ void cpasync16(unsigned dst, const void* src) {
    asm volatile("cp.async.cg.shared.global [%0], [%1], 16;" :: "r"(dst), "l"(src) : "memory");
}
__device__ __forceinline__ void cpcommit() {
    asm volatile("cp.async.commit_group;" ::: "memory");
}
template <int N>
__device__ __forceinline__ void cpwait() {
    asm volatile("cp.async.wait_group %0;" :: "n"(N) : "memory");
}

// ---------------------------------------------------------------------------
// MEGA: bridge -> bar -> gates -> bar -> GRU -> bar -> proj (persistent
// chunk loop) -> bar -> exp-sum -> bar -> broadcast stores.
// One launch; 296 co-resident blocks; each phase keeps its proven body.
// ---------------------------------------------------------------------------
__global__ __launch_bounds__(256, 2)
void k_mega(const int* __restrict__ input,
            const float* __restrict__ hidden,
            const float* __restrict__ emb,
            const float* __restrict__ bridge_w,
            const float* __restrict__ bridge_b,
            const float* __restrict__ w_ih,
            const float* __restrict__ w_hh,
            const float* __restrict__ b_ih,
            const float* __restrict__ b_hh,
            const float* __restrict__ proj_w,
            const float* __restrict__ proj_b,
            float* __restrict__ out) {
    __shared__ float bw[L];
    __shared__ float part[4][64];
    __shared__ float sbin[B];
    extern __shared__ char smem_raw[];
    u64*  hs = (u64*)smem_raw;                    // 64KB, swizzled (phase D)
    char* pf = smem_raw + 65536;                  // 32KB staging (phase D)

    int tid  = threadIdx.x;
    int warp = tid >> 5;
    int lane = tid & 31;

    if (blockIdx.x == 0 && tid < B) g_sum[tid] = 0.f;   // replay-safe re-zero
    if (tid < L) bw[tid] = bridge_w[tid];
    __syncthreads();

    // ======== phase A: x0 = relu(emb[tok]); h0 = bridge(hidden) ========
    {
        int slot = tid & 63;
        int lc   = tid >> 6;
        int i0 = blockIdx.x * 64;
        if (i0 < B * H) {
            int i = i0 + slot;
            int b = i >> 10;
            int h = i & (H - 1);
            const float* hp = hidden + (size_t)b * L * H + (size_t)(lc * 32) * H + h;
            float a0 = 0.f, a1 = 0.f, a2 = 0.f, a3 = 0.f;
            #pragma unroll
            for (int l = 0; l < 32; l += 4) {
                a0 += __ldcs(hp + (l + 0) * H) * bw[lc * 32 + l + 0];
                a1 += __ldcs(hp + (l + 1) * H) * bw[lc * 32 + l + 1];
                a2 += __ldcs(hp + (l + 2) * H) * bw[lc * 32 + l + 2];
                a3 += __ldcs(hp + (l + 3) * H) * bw[lc * 32 + l + 3];
            }
            part[lc][slot] = (a0 + a1) + (a2 + a3);
            __syncthreads();
            if (lc == 0) {
                int tok = input[b * L];
                g_x0[i] = fmaxf(emb[(size_t)tok * H + h], 0.0f);
                g_h0[i] = (part[0][slot] + part[1][slot]) +
                          (part[2][slot] + part[3][slot]) + bridge_b[0];
            }
        }
    }

    grid_barrier();

    // ======== phase B: gi = x0 @ w_ih^T + b_ih ; gh = h0 @ w_hh^T + b_hh ===
    {
        int j0 = (blockIdx.x * 8 + warp) * 2;
        if (j0 < 3 * H) {
            float ai0[B], ai1[B], ah0[B], ah1[B];
            #pragma unroll
            for (int b = 0; b < B; b++) { ai0[b] = ai1[b] = ah0[b] = ah1[b] = 0.f; }

            for (int i = 0; i < 8; i++) {
                int k = i * 128 + lane * 4;
                float4 wi0 = *(const float4*)(w_ih + (size_t)(j0 + 0) * H + k);
                float4 wi1 = *(const float4*)(w_ih + (size_t)(j0 + 1) * H + k);
                float4 wh0 = *(const float4*)(w_hh + (size_t)(j0 + 0) * H + k);
                float4 wh1 = *(const float4*)(w_hh + (size_t)(j0 + 1) * H + k);
                #pragma unroll
                for (int b = 0; b < B; b++) {
                    float4 x = *(const float4*)(g_x0 + b * H + k);
                    float4 h = *(const float4*)(g_h0 + b * H + k);
                    ai0[b] += wi0.x * x.x + wi0.y * x.y + wi0.z * x.z + wi0.w * x.w;
                    ai1[b] += wi1.x * x.x + wi1.y * x.y + wi1.z * x.z + wi1.w * x.w;
                    ah0[b] += wh0.x * h.x + wh0.y * h.y + wh0.z * h.z + wh0.w * h.w;
                    ah1[b] += wh1.x * h.x + wh1.y * h.y + wh1.z * h.z + wh1.w * h.w;
                }
            }

            #pragma unroll
            for (int b = 0; b < B; b++) {
                #pragma unroll
                for (int o = 16; o; o >>= 1) {
                    ai0[b] += __shfl_xor_sync(0xffffffffu, ai0[b], o);
                    ai1[b] += __shfl_xor_sync(0xffffffffu, ai1[b], o);
                    ah0[b] += __shfl_xor_sync(0xffffffffu, ah0[b], o);
                    ah1[b] += __shfl_xor_sync(0xffffffffu, ah1[b], o);
                }
            }

            if (lane == 0) {
                float bi0 = b_ih[j0], bi1 = b_ih[j0 + 1];
                float bh0 = b_hh[j0], bh1 = b_hh[j0 + 1];
                #pragma unroll
                for (int b = 0; b < B; b++) {
                    g_gi[b * 3 * H + j0]     = ai0[b] + bi0;
                    g_gi[b * 3 * H + j0 + 1] = ai1[b] + bi1;
                    g_gh[b * 3 * H + j0]     = ah0[b] + bh0;
                    g_gh[b * 3 * H + j0 + 1] = ah1[b] + bh1;
                }
            }
        }
    }

    grid_barrier();

    // ======== phase C: GRU cell -> h1 ========
    {
        int gtid = blockIdx.x * 256 + tid;
        if (gtid < B * H) {
            int b = gtid >> 10;
            int h = gtid & (H - 1);
            int base = b * 3 * H + h;
            float ir = g_gi[base], iz = g_gi[base + H], in_ = g_gi[base + 2 * H];
            float hr = g_gh[base], hz = g_gh[base + H], hn  = g_gh[base + 2 * H];
            float r = 1.f / (1.f + expf(-(ir + hr)));
            float z = 1.f / (1.f + expf(-(iz + hz)));
            float n = tanhf(in_ + r * hn);
            g_h1[gtid] = (1.f - z) * n + z * g_h0[gtid];
        }
    }

    grid_barrier();

    // ======== phase D: proj GEMV (persistent chunk loop) ========
    for (int i = tid; i < BP * H; i += 256) {
        int bp = i >> 10;
        int k  = i & (H - 1);
        unsigned lo = __float_as_uint(g_h1[(2 * bp) * H + k]);
        unsigned hi = __float_as_uint(g_h1[(2 * bp + 1) * H + k]);
        hs[swz(i)] = ((u64)hi << 32) | (u64)lo;
    }
    __syncthreads();

    for (int c = blockIdx.x; c < NCHUNK; c += NBLK) {
        int v0 = (c * 8 + warp) * 4;
        if (v0 >= V) continue;

        int r1 = min(v0 + 1, V - 1);
        int r2 = min(v0 + 2, V - 1);
        int r3 = min(v0 + 3, V - 1);
        const char* w0 = (const char*)(proj_w + (size_t)v0 * H);
        const char* w1 = (const char*)(proj_w + (size_t)r1 * H);
        const char* w2 = (const char*)(proj_w + (size_t)r2 * H);
        const char* w3 = (const char*)(proj_w + (size_t)r3 * H);

        char* pfw = pf + warp * 4096 + lane * 16;
        unsigned pfw_s = (unsigned)__cvta_generic_to_shared(pfw);

        u64 a0[BP], a1[BP], a2[BP], a3[BP];
        #pragma unroll
        for (int bp = 0; bp < BP; bp++) { a0[bp] = a1[bp] = a2[bp] = a3[bp] = 0ull; }

        {
            int off = lane * 16;
            cpasync16(pfw_s + 0 * 2048 + 0 * 512, w0 + off);
            cpasync16(pfw_s + 0 * 2048 + 1 * 512, w1 + off);
            cpasync16(pfw_s + 0 * 2048 + 2 * 512, w2 + off);
            cpasync16(pfw_s + 0 * 2048 + 3 * 512, w3 + off);
            cpcommit();
            cpasync16(pfw_s + 1 * 2048 + 0 * 512, w0 + 512 + off);
            cpasync16(pfw_s + 1 * 2048 + 1 * 512, w1 + 512 + off);
            cpasync16(pfw_s + 1 * 2048 + 2 * 512, w2 + 512 + off);
            cpasync16(pfw_s + 1 * 2048 + 3 * 512, w3 + 512 + off);
            cpcommit();
        }

        #pragma unroll
        for (int i = 0; i < 8; i++) {
            const int buf = i & 1;
            if (i < 6) cpwait<1>(); else cpwait<0>();

            const char* pb = pf + warp * 4096 + buf * 2048 + lane * 16;
            float4 p0 = *(const float4*)(pb + 0 * 512);
            float4 p1 = *(const float4*)(pb + 1 * 512);
            float4 p2 = *(const float4*)(pb + 2 * 512);
            float4 p3 = *(const float4*)(pb + 3 * 512);
            u64 q0x = dup2(p0.x), q0y = dup2(p0.y), q0z = dup2(p0.z), q0w = dup2(p0.w);
            u64 q1x = dup2(p1.x), q1y = dup2(p1.y), q1z = dup2(p1.z), q1w = dup2(p1.w);
            u64 q2x = dup2(p2.x), q2y = dup2(p2.y), q2z = dup2(p2.z), q2w = dup2(p2.w);
            u64 q3x = dup2(p3.x), q3y = dup2(p3.y), q3z = dup2(p3.z), q3w = dup2(p3.w);

            if (i < 6) {
                int off = (i + 2) * 512 + lane * 16;
                unsigned d = pfw_s + buf * 2048;
                cpasync16(d + 0 * 512, w0 + off);
                cpasync16(d + 1 * 512, w1 + off);
                cpasync16(d + 2 * 512, w2 + off);
                cpasync16(d + 3 * 512, w3 + off);
                cpcommit();
            }

            int kq = i * 32 + lane;
            #pragma unroll
            for (int bp = 0; bp < BP; bp++) {
                int idx = bp * 1024 + kq * 4;
                int f   = ((idx >> 4) & 1) << 1;
                ulonglong2 xa = *(const ulonglong2*)(hs + (idx ^ f));
                ulonglong2 xb = *(const ulonglong2*)(hs + ((idx + 2) ^ f));
                ffma2(a0[bp], q0x, xa.x); ffma2(a0[bp], q0y, xa.y);
                ffma2(a0[bp], q0z, xb.x); ffma2(a0[bp], q0w, xb.y);
                ffma2(a1[bp], q1x, xa.x); ffma2(a1[bp], q1y, xa.y);
                ffma2(a1[bp], q1z, xb.x); ffma2(a1[bp], q1w, xb.y);
                ffma2(a2[bp], q2x, xa.x); ffma2(a2[bp], q2y, xa.y);
                ffma2(a2[bp], q2z, xb.x); ffma2(a2[bp], q2w, xb.y);
                ffma2(a3[bp], q3x, xa.x); ffma2(a3[bp], q3y, xa.y);
                ffma2(a3[bp], q3z, xb.x); ffma2(a3[bp], q3w, xb.y);
            }
        }

        float pb0 = proj_b[v0];
        float pb1 = proj_b[r1];
        float pb2 = proj_b[r2];
        float pb3 = proj_b[r3];

        #pragma unroll
        for (int bp = 0; bp < BP; bp++) {
            float s0a = lo2(a0[bp]), s0b = hi2(a0[bp]);
            float s1a = lo2(a1[bp]), s1b = hi2(a1[bp]);
            float s2a = lo2(a2[bp]), s2b = hi2(a2[bp]);
            float s3a = lo2(a3[bp]), s3b = hi2(a3[bp]);
            #pragma unroll
            for (int o = 16; o; o >>= 1) {
                s0a += __shfl_xor_sync(0xffffffffu, s0a, o);
                s0b += __shfl_xor_sync(0xffffffffu, s0b, o);
                s1a += __shfl_xor_sync(0xffffffffu, s1a, o);
                s1b += __shfl_xor_sync(0xffffffffu, s1b, o);
                s2a += __shfl_xor_sync(0xffffffffu, s2a, o);
                s2b += __shfl_xor_sync(0xffffffffu, s2b, o);
                s3a += __shfl_xor_sync(0xffffffffu, s3a, o);
                s3b += __shfl_xor_sync(0xffffffffu, s3b, o);
            }
            if (lane == 0) {
                float* lga = g_logits + (size_t)(2 * bp) * V;
                float* lgb = g_logits + (size_t)(2 * bp + 1) * V;
                lga[v0] = s0a + pb0;  lgb[v0] = s0b + pb0;
                if (v0 + 1 < V) { lga[v0 + 1] = s1a + pb1;  lgb[v0 + 1] = s1b + pb1; }
                if (v0 + 2 < V) { lga[v0 + 2] = s2a + pb2;  lgb[v0 + 2] = s2b + pb2; }
                if (v0 + 3 < V) { lga[v0 + 3] = s3a + pb3;  lgb[v0 + 3] = s3b + pb3; }
            }
        }
    }

    grid_barrier();

    // ======== phase E: exp-sum (no max-shift; |logit| small) ========
    if (tid < B) sbin[tid] = 0.f;
    __syncthreads();
    for (int idx = blockIdx.x * 256 + tid; idx < NTASK; idx += NBLK * 256) {
        int b = idx / (NQ + 1);
        int j = idx - b * (NQ + 1);
        const float* lg = g_logits + (size_t)b * V;
        float s;
        if (j < NQ) {
            s = (expf(lg[4 * j + 0]) + expf(lg[4 * j + 1])) +
                (expf(lg[4 * j + 2]) + expf(lg[4 * j + 3]));
        } else {
            s = (expf(lg[4 * NQ + 0]) + expf(lg[4 * NQ + 1])) +
                (expf(lg[4 * NQ + 2]) + expf(lg[4 * NQ + 3])) +
                expf(lg[4 * NQ + 4]);
        }
        atomicAdd(&sbin[b], s);
    }
    __syncthreads();
    if (tid < B) atomicAdd(&g_sum[tid], sbin[tid]);

    grid_barrier();

    // ======== phase F: broadcast stores (aligned quads, streaming) ========
    for (int idx = blockIdx.x * 256 + tid; idx < NTASK; idx += NBLK * 256) {
        int b = idx / (NQ + 1);
        int j = idx - b * (NQ + 1);
        float sub = logf(__ldcg((const float*)&g_sum[b]));
        const float* lg = g_logits + (size_t)b * V;
        float* ob = out + (size_t)b * T * V;

        if (j < NQ) {
            float q0 = lg[4 * j + 0] - sub, q1 = lg[4 * j + 1] - sub;
            float q2 = lg[4 * j + 2] - sub, q3 = lg[4 * j + 3] - sub;
            float q4 = lg[4 * j + 4] - sub, q5 = lg[4 * j + 5] - sub;
            float q6 = lg[4 * j + 6] - sub;
            float4 v0 = make_float4(q0, q1, q2, q3);   // s=0 (r%4==0)
            float4 v3 = make_float4(q3, q4, q5, q6);   // s=3 (r%4==1)
            float4 v2 = make_float4(q2, q3, q4, q5);   // s=2 (r%4==2)
            float4 v1 = make_float4(q1, q2, q3, q4);   // s=1 (r%4==3)

            // r = b*127 + t ≡ 3b + t (mod 4); r≡c ⇔ t ≡ c + b (mod 4)
            int t0;
            t0 = (0 + b) & 3;
            #pragma unroll 4
            for (int t = t0; t < T; t += 4) __stcs((float4*)(ob + (size_t)t * V + 4 * j + 0), v0);
            t0 = (1 + b) & 3;
            #pragma unroll 4
            for (int t = t0; t < T; t += 4) __stcs((float4*)(ob + (size_t)t * V + 4 * j + 3), v3);
            t0 = (2 + b) & 3;
            #pragma unroll 4
            for (int t = t0; t < T; t += 4) __stcs((float4*)(ob + (size_t)t * V + 4 * j + 2), v2);
            t0 = (3 + b) & 3;
            #pragma unroll 4
            for (int t = t0; t < T; t += 4) __stcs((float4*)(ob + (size_t)t * V + 4 * j + 1), v1);
        } else {
            float h0 = lg[0] - sub, h1 = lg[1] - sub, h2 = lg[2] - sub;
            float e0 = lg[4 * NQ + 0] - sub, e1 = lg[4 * NQ + 1] - sub;
            float e2 = lg[4 * NQ + 2] - sub, e3 = lg[4 * NQ + 3] - sub;
            float e4 = lg[4 * NQ + 4] - sub;
            for (int t = 0; t < T; t++) {
                int c = (3 * b + t) & 3;        // r & 3
                int sshift = (4 - c) & 3;
                float* row = ob + (size_t)t * V;
                if (sshift > 0) __stcs(row + 0, h0);
                if (sshift > 1) __stcs(row + 1, h1);
                if (sshift > 2) __stcs(row + 2, h2);
                if (sshift == 0) __stcs(row + 4 * NQ + 0, e0);
                if (sshift <= 1) __stcs(row + 4 * NQ + 1, e1);
                if (sshift <= 2) __stcs(row + 4 * NQ + 2, e2);
                if (sshift <= 3) __stcs(row + 4 * NQ + 3, e3);
                __stcs(row + 4 * NQ + 4, e4);
            }
        }
    }
}

// ---------------------------------------------------------------------------
extern "C" void kernel_launch(void* const* d_in, const int* in_sizes, int n_in,
                              void* d_out, int out_size) {
    const int*   input    = (const int*)d_in[0];
    const float* hidden   = (const float*)d_in[1];
    const float* emb      = (const float*)d_in[2];
    const float* bridge_w = (const float*)d_in[3];
    const float* bridge_b = (const float*)d_in[4];
    const float* w_ih     = (const float*)d_in[5];
    const float* w_hh     = (const float*)d_in[6];
    const float* b_ih     = (const float*)d_in[7];
    const float* b_hh     = (const float*)d_in[8];
    const float* proj_w   = (const float*)d_in[9];
    const float* proj_b   = (const float*)d_in[10];
    float* out = (float*)d_out;

    const int dyn_smem = 65536 + 32768;   // hs + pf
    cudaFuncSetAttribute(k_mega, cudaFuncAttributeMaxDynamicSharedMemorySize,
                         dyn_smem);

    k_mega<<<NBLK, 256, dyn_smem>>>(input, hidden, emb, bridge_w, bridge_b,
                                    w_ih, w_hh, b_ih, b_hh, proj_w, proj_b, out);
}

// round 15
// speedup vs baseline: 1.0461x; 1.0461x over previous
#include <cuda_runtime.h>
#include <math.h>

#define B 16
#define L 128
#define H 1024
#define V 50257
#define T (L-1)
#define BP (B/2)
#define NQ 12563             // quads per row; 4*NQ = 50252
#define NB123 296            // fused front kernel: exactly 2 CTAs/SM x 148

typedef unsigned long long u64;

// ---- scratch (no allocations allowed) ----
__device__ float g_x0[B * H];
__device__ float g_h0[B * H];
__device__ float g_gi[B * 3 * H];
__device__ float g_gh[B * 3 * H];
__device__ float g_h1[B * H];
__device__ float g_logits[(size_t)B * V];
__device__ float g_sum[B];

// grid barrier state (generation counter -> graph-replay safe)
__device__ volatile unsigned g_bar_gen;
__device__ unsigned g_bar_cnt;

__device__ __forceinline__ void grid_barrier(int nblocks) {
    __syncthreads();
    if (threadIdx.x == 0) {
        unsigned gen = g_bar_gen;
        __threadfence();
        if (atomicAdd(&g_bar_cnt, 1) == (unsigned)(nblocks - 1)) {
            g_bar_cnt = 0;
            __threadfence();
            g_bar_gen = gen + 1;
        } else {
            while (g_bar_gen == gen) { }
        }
    }
    __syncthreads();
}

// packed f32x2 FMA: d = a*b + d (2 MACs / SASS FFMA2)
__device__ __forceinline__ void ffma2(u64 &d, u64 a, u64 b) {
    asm("fma.rn.f32x2 %0, %1, %2, %0;" : "+l"(d) : "l"(a), "l"(b));
}
__device__ __forceinline__ u64 dup2(float f) {
    u64 r;
    asm("mov.b64 %0, {%1, %1};" : "=l"(r) : "f"(f));
    return r;
}
__device__ __forceinline__ float lo2(u64 a) { return __uint_as_float((unsigned)a); }
__device__ __forceinline__ float hi2(u64 a) { return __uint_as_float((unsigned)(a >> 32)); }

// XOR swizzle on u64 index: flips the 16B-granule bit on alternating 128B lines
__device__ __forceinline__ int swz(int i) { return i ^ (((i >> 4) & 1) << 1); }

// cp.async 16B, L2-only path (streaming)
__device__ __forceinline__ void cpasync16(unsigned dst, const void* src) {
    asm volatile("cp.async.cg.shared.global [%0], [%1], 16;" :: "r"(dst), "l"(src) : "memory");
}
__device__ __forceinline__ void cpcommit() {
    asm volatile("cp.async.commit_group;" ::: "memory");
}
template <int N>
__device__ __forceinline__ void cpwait() {
    asm volatile("cp.async.wait_group %0;" :: "n"(N) : "memory");
}

// ---------------------------------------------------------------------------
// K123: fused embed+bridge -> barrier -> gates GEMV (with weight prefetch)
// -> barrier -> GRU cell. Zeroes g_sum for k4's epilogue atomics.
// ---------------------------------------------------------------------------
__global__ __launch_bounds__(256, 2)
void k123_front(const int* __restrict__ input,
                const float* __restrict__ hidden,
                const float* __restrict__ emb,
                const float* __restrict__ bridge_w,
                const float* __restrict__ bridge_b,
                const float* __restrict__ w_ih,
                const float* __restrict__ w_hh,
                const float* __restrict__ b_ih,
                const float* __restrict__ b_hh) {
    __shared__ float bw[L];
    __shared__ float part[4][64];
    int tid = threadIdx.x;
    if (tid < L) bw[tid] = bridge_w[tid];
    if (blockIdx.x == 0 && tid < B) g_sum[tid] = 0.f;
    __syncthreads();

    // ---- phase A: x0 = relu(emb[tok]); h0 = bridge(hidden) ----
    int slot = tid & 63;
    int lc   = tid >> 6;
    int i0 = blockIdx.x * 64;
    if (i0 < B * H) {
        int i = i0 + slot;
        int b = i >> 10;
        int h = i & (H - 1);
        const float* hp = hidden + (size_t)b * L * H + (size_t)(lc * 32) * H + h;
        float a0 = 0.f, a1 = 0.f, a2 = 0.f, a3 = 0.f;
        #pragma unroll
        for (int l = 0; l < 32; l += 4) {
            a0 += __ldcs(hp + (l + 0) * H) * bw[lc * 32 + l + 0];
            a1 += __ldcs(hp + (l + 1) * H) * bw[lc * 32 + l + 1];
            a2 += __ldcs(hp + (l + 2) * H) * bw[lc * 32 + l + 2];
            a3 += __ldcs(hp + (l + 3) * H) * bw[lc * 32 + l + 3];
        }
        part[lc][slot] = (a0 + a1) + (a2 + a3);
        __syncthreads();
        if (lc == 0) {
            int tok = input[b * L];
            g_x0[i] = fmaxf(emb[(size_t)tok * H + h], 0.0f);
            g_h0[i] = (part[0][slot] + part[1][slot]) +
                      (part[2][slot] + part[3][slot]) + bridge_b[0];
        }
    }

    grid_barrier(NB123);

    // ---- phase B: gi = x0 @ w_ih^T + b_ih ; gh = h0 @ w_hh^T + b_hh ----
    {
        int warp = tid >> 5;
        int lane = tid & 31;
        int j0 = (blockIdx.x * 8 + warp) * 2;
        if (j0 < 3 * H) {
            float ai0[B], ai1[B], ah0[B], ah1[B];
            #pragma unroll
            for (int b = 0; b < B; b++) { ai0[b] = ai1[b] = ah0[b] = ah1[b] = 0.f; }

            const float* pwi0 = w_ih + (size_t)(j0 + 0) * H;
            const float* pwi1 = w_ih + (size_t)(j0 + 1) * H;
            const float* pwh0 = w_hh + (size_t)(j0 + 0) * H;
            const float* pwh1 = w_hh + (size_t)(j0 + 1) * H;

            // 1-deep prefetch pipeline on the weight loads
            int k = lane * 4;
            float4 wi0 = *(const float4*)(pwi0 + k);
            float4 wi1 = *(const float4*)(pwi1 + k);
            float4 wh0 = *(const float4*)(pwh0 + k);
            float4 wh1 = *(const float4*)(pwh1 + k);

            #pragma unroll
            for (int i = 0; i < 8; i++) {
                float4 cwi0 = wi0, cwi1 = wi1, cwh0 = wh0, cwh1 = wh1;
                int kc = i * 128 + lane * 4;
                if (i < 7) {
                    int kn = kc + 128;
                    wi0 = *(const float4*)(pwi0 + kn);
                    wi1 = *(const float4*)(pwi1 + kn);
                    wh0 = *(const float4*)(pwh0 + kn);
                    wh1 = *(const float4*)(pwh1 + kn);
                }
                #pragma unroll
                for (int b = 0; b < B; b++) {
                    float4 x = *(const float4*)(g_x0 + b * H + kc);
                    float4 h = *(const float4*)(g_h0 + b * H + kc);
                    ai0[b] += cwi0.x * x.x + cwi0.y * x.y + cwi0.z * x.z + cwi0.w * x.w;
                    ai1[b] += cwi1.x * x.x + cwi1.y * x.y + cwi1.z * x.z + cwi1.w * x.w;
                    ah0[b] += cwh0.x * h.x + cwh0.y * h.y + cwh0.z * h.z + cwh0.w * h.w;
                    ah1[b] += cwh1.x * h.x + cwh1.y * h.y + cwh1.z * h.z + cwh1.w * h.w;
                }
            }

            #pragma unroll
            for (int b = 0; b < B; b++) {
                #pragma unroll
                for (int o = 16; o; o >>= 1) {
                    ai0[b] += __shfl_xor_sync(0xffffffffu, ai0[b], o);
                    ai1[b] += __shfl_xor_sync(0xffffffffu, ai1[b], o);
                    ah0[b] += __shfl_xor_sync(0xffffffffu, ah0[b], o);
                    ah1[b] += __shfl_xor_sync(0xffffffffu, ah1[b], o);
                }
            }

            if (lane == 0) {
                float bi0 = b_ih[j0], bi1 = b_ih[j0 + 1];
                float bh0 = b_hh[j0], bh1 = b_hh[j0 + 1];
                #pragma unroll
                for (int b = 0; b < B; b++) {
                    g_gi[b * 3 * H + j0]     = ai0[b] + bi0;
                    g_gi[b * 3 * H + j0 + 1] = ai1[b] + bi1;
                    g_gh[b * 3 * H + j0]     = ah0[b] + bh0;
                    g_gh[b * 3 * H + j0 + 1] = ah1[b] + bh1;
                }
            }
        }
    }

    grid_barrier(NB123);

    // ---- phase C: GRU cell -> h1 ----
    {
        int gtid = blockIdx.x * 256 + tid;
        if (gtid < B * H) {
            int b = gtid >> 10;
            int h = gtid & (H - 1);
            int base = b * 3 * H + h;
            float ir = g_gi[base], iz = g_gi[base + H], in_ = g_gi[base + 2 * H];
            float hr = g_gh[base], hz = g_gh[base + H], hn  = g_gh[base + 2 * H];
            float r = 1.f / (1.f + expf(-(ir + hr)));
            float z = 1.f / (1.f + expf(-(iz + hz)));
            float n = tanhf(in_ + r * hn);
            g_h1[gtid] = (1.f - z) * n + z * g_h0[gtid];
        }
    }
}

// ---------------------------------------------------------------------------
// K4: logits[b,v] = h1[b,:] . proj_w[v,:] + proj_b[v]  +  fused exp-sum.
// Batch-packed f32x2 + swizzled smem h1 + cp.async proj_w (committed), plus:
// epilogue stages the 64 biased sums per warp in smem, lanes 0-15 exp 4
// values each (their batch), smem bins, 16 global atomics per block.
// Removes k6's sum pass and grid barrier entirely.
// ---------------------------------------------------------------------------
__global__ __launch_bounds__(256, 2)
void k4_proj(const float* __restrict__ proj_w,
             const float* __restrict__ proj_b) {
    __shared__ float sbin[B];
    __shared__ float wbuf[8][64];
    extern __shared__ char smem_raw[];
    u64*  hs = (u64*)smem_raw;                    // 64KB, swizzled
    char* pf = smem_raw + 65536;                  // 32KB staging

    int tid  = threadIdx.x;
    if (tid < B) sbin[tid] = 0.f;
    for (int i = tid; i < BP * H; i += 256) {
        int bp = i >> 10;
        int k  = i & (H - 1);
        unsigned lo = __float_as_uint(g_h1[(2 * bp) * H + k]);
        unsigned hi = __float_as_uint(g_h1[(2 * bp + 1) * H + k]);
        hs[swz(i)] = ((u64)hi << 32) | (u64)lo;
    }
    __syncthreads();

    int warp = tid >> 5;
    int lane = tid & 31;
    int v0 = (blockIdx.x * 8 + warp) * 4;

    if (v0 < V) {
        int r1 = min(v0 + 1, V - 1);
        int r2 = min(v0 + 2, V - 1);
        int r3 = min(v0 + 3, V - 1);
        const char* w0 = (const char*)(proj_w + (size_t)v0 * H);
        const char* w1 = (const char*)(proj_w + (size_t)r1 * H);
        const char* w2 = (const char*)(proj_w + (size_t)r2 * H);
        const char* w3 = (const char*)(proj_w + (size_t)r3 * H);

        char* pfw = pf + warp * 4096 + lane * 16;
        unsigned pfw_s = (unsigned)__cvta_generic_to_shared(pfw);

        u64 a0[BP], a1[BP], a2[BP], a3[BP];
        #pragma unroll
        for (int bp = 0; bp < BP; bp++) { a0[bp] = a1[bp] = a2[bp] = a3[bp] = 0ull; }

        {
            int off = lane * 16;
            cpasync16(pfw_s + 0 * 2048 + 0 * 512, w0 + off);
            cpasync16(pfw_s + 0 * 2048 + 1 * 512, w1 + off);
            cpasync16(pfw_s + 0 * 2048 + 2 * 512, w2 + off);
            cpasync16(pfw_s + 0 * 2048 + 3 * 512, w3 + off);
            cpcommit();
            cpasync16(pfw_s + 1 * 2048 + 0 * 512, w0 + 512 + off);
            cpasync16(pfw_s + 1 * 2048 + 1 * 512, w1 + 512 + off);
            cpasync16(pfw_s + 1 * 2048 + 2 * 512, w2 + 512 + off);
            cpasync16(pfw_s + 1 * 2048 + 3 * 512, w3 + 512 + off);
            cpcommit();
        }

        #pragma unroll
        for (int i = 0; i < 8; i++) {
            const int buf = i & 1;
            if (i < 6) cpwait<1>(); else cpwait<0>();

            const char* pb = pf + warp * 4096 + buf * 2048 + lane * 16;
            float4 p0 = *(const float4*)(pb + 0 * 512);
            float4 p1 = *(const float4*)(pb + 1 * 512);
            float4 p2 = *(const float4*)(pb + 2 * 512);
            float4 p3 = *(const float4*)(pb + 3 * 512);
            u64 q0x = dup2(p0.x), q0y = dup2(p0.y), q0z = dup2(p0.z), q0w = dup2(p0.w);
            u64 q1x = dup2(p1.x), q1y = dup2(p1.y), q1z = dup2(p1.z), q1w = dup2(p1.w);
            u64 q2x = dup2(p2.x), q2y = dup2(p2.y), q2z = dup2(p2.z), q2w = dup2(p2.w);
            u64 q3x = dup2(p3.x), q3y = dup2(p3.y), q3z = dup2(p3.z), q3w = dup2(p3.w);

            if (i < 6) {
                int off = (i + 2) * 512 + lane * 16;
                unsigned d = pfw_s + buf * 2048;
                cpasync16(d + 0 * 512, w0 + off);
                cpasync16(d + 1 * 512, w1 + off);
                cpasync16(d + 2 * 512, w2 + off);
                cpasync16(d + 3 * 512, w3 + off);
                cpcommit();
            }

            int kq = i * 32 + lane;
            #pragma unroll
            for (int bp = 0; bp < BP; bp++) {
                int idx = bp * 1024 + kq * 4;
                int f   = ((idx >> 4) & 1) << 1;
                ulonglong2 xa = *(const ulonglong2*)(hs + (idx ^ f));
                ulonglong2 xb = *(const ulonglong2*)(hs + ((idx + 2) ^ f));
                ffma2(a0[bp], q0x, xa.x); ffma2(a0[bp], q0y, xa.y);
                ffma2(a0[bp], q0z, xb.x); ffma2(a0[bp], q0w, xb.y);
                ffma2(a1[bp], q1x, xa.x); ffma2(a1[bp], q1y, xa.y);
                ffma2(a1[bp], q1z, xb.x); ffma2(a1[bp], q1w, xb.y);
                ffma2(a2[bp], q2x, xa.x); ffma2(a2[bp], q2y, xa.y);
                ffma2(a2[bp], q2z, xb.x); ffma2(a2[bp], q2w, xb.y);
                ffma2(a3[bp], q3x, xa.x); ffma2(a3[bp], q3y, xa.y);
                ffma2(a3[bp], q3z, xb.x); ffma2(a3[bp], q3w, xb.y);
            }
        }

        float pb0 = proj_b[v0];
        float pb1 = proj_b[r1];
        float pb2 = proj_b[r2];
        float pb3 = proj_b[r3];
        bool val1 = (v0 + 1 < V), val2 = (v0 + 2 < V), val3 = (v0 + 3 < V);

        #pragma unroll
        for (int bp = 0; bp < BP; bp++) {
            float s0a = lo2(a0[bp]), s0b = hi2(a0[bp]);
            float s1a = lo2(a1[bp]), s1b = hi2(a1[bp]);
            float s2a = lo2(a2[bp]), s2b = hi2(a2[bp]);
            float s3a = lo2(a3[bp]), s3b = hi2(a3[bp]);
            #pragma unroll
            for (int o = 16; o; o >>= 1) {
                s0a += __shfl_xor_sync(0xffffffffu, s0a, o);
                s0b += __shfl_xor_sync(0xffffffffu, s0b, o);
                s1a += __shfl_xor_sync(0xffffffffu, s1a, o);
                s1b += __shfl_xor_sync(0xffffffffu, s1b, o);
                s2a += __shfl_xor_sync(0xffffffffu, s2a, o);
                s2b += __shfl_xor_sync(0xffffffffu, s2b, o);
                s3a += __shfl_xor_sync(0xffffffffu, s3a, o);
                s3b += __shfl_xor_sync(0xffffffffu, s3b, o);
            }
            if (lane == 0) {
                float* lga = g_logits + (size_t)(2 * bp) * V;
                float* lgb = g_logits + (size_t)(2 * bp + 1) * V;
                lga[v0] = s0a + pb0;  lgb[v0] = s0b + pb0;
                if (val1) { lga[v0 + 1] = s1a + pb1;  lgb[v0 + 1] = s1b + pb1; }
                if (val2) { lga[v0 + 2] = s2a + pb2;  lgb[v0 + 2] = s2b + pb2; }
                if (val3) { lga[v0 + 3] = s3a + pb3;  lgb[v0 + 3] = s3b + pb3; }
                // stage biased sums for exp (invalid rows -> -1e30 -> exp=0)
                wbuf[warp][bp * 8 + 0] = s0a + pb0;
                wbuf[warp][bp * 8 + 1] = s0b + pb0;
                wbuf[warp][bp * 8 + 2] = val1 ? s1a + pb1 : -1e30f;
                wbuf[warp][bp * 8 + 3] = val1 ? s1b + pb1 : -1e30f;
                wbuf[warp][bp * 8 + 4] = val2 ? s2a + pb2 : -1e30f;
                wbuf[warp][bp * 8 + 5] = val2 ? s2b + pb2 : -1e30f;
                wbuf[warp][bp * 8 + 6] = val3 ? s3a + pb3 : -1e30f;
                wbuf[warp][bp * 8 + 7] = val3 ? s3b + pb3 : -1e30f;
            }
        }
        __syncwarp();
        if (lane < B) {
            int bp = lane >> 1, half = lane & 1;
            float e = (expf(wbuf[warp][bp * 8 + 0 + half]) +
                       expf(wbuf[warp][bp * 8 + 2 + half])) +
                      (expf(wbuf[warp][bp * 8 + 4 + half]) +
                       expf(wbuf[warp][bp * 8 + 6 + half]));
            atomicAdd(&sbin[lane], e);
        }
    }

    __syncthreads();
    if (tid < B) atomicAdd(&g_sum[tid], sbin[tid]);
}

// ---------------------------------------------------------------------------
// K6: out[b,t,v] = logits[b,v] - log(g_sum[b]), broadcast over t, with
// alignment-shifted STG.128 quads + streaming stores. No barrier, no sum
// pass (g_sum completed by k4).
// ---------------------------------------------------------------------------
__global__ void k6_out(float* __restrict__ out) {
    int j = blockIdx.x * 256 + threadIdx.x;
    int b = blockIdx.y;
    if (j > NQ) return;
    float sub = logf(g_sum[b]);
    const float* lg = g_logits + (size_t)b * V;
    float* ob = out + (size_t)b * T * V;

    if (j < NQ) {
        float q0 = lg[4 * j + 0] - sub, q1 = lg[4 * j + 1] - sub;
        float q2 = lg[4 * j + 2] - sub, q3 = lg[4 * j + 3] - sub;
        float q4 = lg[4 * j + 4] - sub, q5 = lg[4 * j + 5] - sub;
        float q6 = lg[4 * j + 6] - sub;
        float4 v0 = make_float4(q0, q1, q2, q3);   // s=0 (r%4==0)
        float4 v3 = make_float4(q3, q4, q5, q6);   // s=3 (r%4==1)
        float4 v2 = make_float4(q2, q3, q4, q5);   // s=2 (r%4==2)
        float4 v1 = make_float4(q1, q2, q3, q4);   // s=1 (r%4==3)

        // r = b*127 + t ≡ 3b + t (mod 4); r≡c ⇔ t ≡ c + b (mod 4)
        int t0;
        t0 = (0 + b) & 3;
        #pragma unroll 4
        for (int t = t0; t < T; t += 4) __stcs((float4*)(ob + (size_t)t * V + 4 * j + 0), v0);
        t0 = (1 + b) & 3;
        #pragma unroll 4
        for (int t = t0; t < T; t += 4) __stcs((float4*)(ob + (size_t)t * V + 4 * j + 3), v3);
        t0 = (2 + b) & 3;
        #pragma unroll 4
        for (int t = t0; t < T; t += 4) __stcs((float4*)(ob + (size_t)t * V + 4 * j + 2), v2);
        t0 = (3 + b) & 3;
        #pragma unroll 4
        for (int t = t0; t < T; t += 4) __stcs((float4*)(ob + (size_t)t * V + 4 * j + 1), v1);
    } else {
        float h0 = lg[0] - sub, h1 = lg[1] - sub, h2 = lg[2] - sub;
        float e0 = lg[4 * NQ + 0] - sub, e1 = lg[4 * NQ + 1] - sub;
        float e2 = lg[4 * NQ + 2] - sub, e3 = lg[4 * NQ + 3] - sub;
        float e4 = lg[4 * NQ + 4] - sub;
        for (int t = 0; t < T; t++) {
            int c = (3 * b + t) & 3;        // r & 3
            int sshift = (4 - c) & 3;
            float* row = ob + (size_t)t * V;
            if (sshift > 0) __stcs(row + 0, h0);
            if (sshift > 1) __stcs(row + 1, h1);
            if (sshift > 2) __stcs(row + 2, h2);
            if (sshift == 0) __stcs(row + 4 * NQ + 0, e0);
            if (sshift <= 1) __stcs(row + 4 * NQ + 1, e1);
            if (sshift <= 2) __stcs(row + 4 * NQ + 2, e2);
            if (sshift <= 3) __stcs(row + 4 * NQ + 3, e3);
            __stcs(row + 4 * NQ + 4, e4);
        }
    }
}

// ---------------------------------------------------------------------------
extern "C" void kernel_launch(void* const* d_in, const int* in_sizes, int n_in,
                              void* d_out, int out_size) {
    const int*   input    = (const int*)d_in[0];
    const float* hidden   = (const float*)d_in[1];
    const float* emb      = (const float*)d_in[2];
    const float* bridge_w = (const float*)d_in[3];
    const float* bridge_b = (const float*)d_in[4];
    const float* w_ih     = (const float*)d_in[5];
    const float* w_hh     = (const float*)d_in[6];
    const float* b_ih     = (const float*)d_in[7];
    const float* b_hh     = (const float*)d_in[8];
    const float* proj_w   = (const float*)d_in[9];
    const float* proj_b   = (const float*)d_in[10];
    float* out = (float*)d_out;

    const int k4_smem = 65536 + 32768;
    cudaFuncSetAttribute(k4_proj, cudaFuncAttributeMaxDynamicSharedMemorySize,
                         k4_smem);

    k123_front<<<NB123, 256>>>(input, hidden, emb, bridge_w, bridge_b,
                               w_ih, w_hh, b_ih, b_hh);
    int blocks4 = (V + 31) / 32;
    k4_proj<<<blocks4, 256, k4_smem>>>(proj_w, proj_b);
    dim3 g6(50, B);
    k6_out<<<g6, 256>>>(out);
}